// round 1
// baseline (speedup 1.0000x reference)
#include <cuda_runtime.h>

// TT embedding: vocab = 50*60*60, emb = 8*8*8 = 512, rank 16, T = 2048*64 tokens.
// Strategy:
//   1) detect x dtype (int32 vs int64) at runtime (device flag)
//   2) build pair table m23[(i2*60+i3)][bc][r] = sum_s core2[i2][r][b][s]*core3[i3][s][c]
//      (3600 x 1024 floats = 14.75 MB, L2-resident)
//   3) gather: per token, emb[a][bc] = sum_r core1[i1][a][r] * m23[pair][bc][r]
//      using fma.rn.f32x2 with r paired even/odd so both packed operands are
//      memory-adjacent (no duplication movs).

#define N_PAIRS   3600
#define PAIR_ELEMS 1024            // 64 bc * 16 r
#define C1_ELEMS  6400             // 50*8*16
#define C2_ELEMS  122880           // 60*16*8*16
#define C3_ELEMS  7680             // 60*16*8

__device__ __align__(16) float g_m23[N_PAIRS * PAIR_ELEMS];
__device__ int g_is64;

// ---------------------------------------------------------------------------
// dtype detector: if x is int64 little-endian (values < 2^31), every odd
// 32-bit word is zero. 128 samples -> unambiguous.
// ---------------------------------------------------------------------------
__global__ void detect_kernel(const int* __restrict__ x) {
    if (threadIdx.x == 0 && blockIdx.x == 0) {
        int zeros = 0;
#pragma unroll 1
        for (int k = 1; k < 256; k += 2) zeros += (x[k] == 0);
        g_is64 = (zeros >= 120) ? 1 : 0;
    }
}

// ---------------------------------------------------------------------------
// Pair table: one block per (i2,i3). core2 slice (8KB) + core3 slice (512B)
// staged in smem. 1024 outputs / 128 threads = 8 outputs x 16 FMA each.
// Layout: g_m23[p*1024 + bc*16 + r]  (r fastest -> LDG.128 in gather covers 4 r)
// ---------------------------------------------------------------------------
__global__ void build_table_kernel(const float* __restrict__ core2,
                                   const float* __restrict__ core3) {
    __shared__ __align__(16) float c2s[2048];   // [r][b][s]
    __shared__ __align__(16) float c3s[128];    // [s][c]
    int p  = blockIdx.x;
    int i2 = p / 60;
    int i3 = p - i2 * 60;

    {
        const float4* g = (const float4*)(core2 + i2 * 2048);
        float4* s = (float4*)c2s;
        for (int i = threadIdx.x; i < 512; i += 128) s[i] = g[i];
        if (threadIdx.x < 32)
            ((float4*)c3s)[threadIdx.x] = ((const float4*)(core3 + i3 * 128))[threadIdx.x];
    }
    __syncthreads();

    int bc = threadIdx.x & 63;
    int rh = threadIdx.x >> 6;          // 0 or 1 -> r in [rh*8, rh*8+8)
    int b  = bc >> 3;
    int c  = bc & 7;
    float* dst = g_m23 + p * PAIR_ELEMS + bc * 16 + rh * 8;
#pragma unroll
    for (int rr = 0; rr < 8; rr++) {
        int r = rh * 8 + rr;
        const float* c2row = c2s + r * 128 + b * 16;
        float v = 0.0f;
#pragma unroll
        for (int s = 0; s < 16; s++) v += c2row[s] * c3s[s * 8 + c];
        dst[rr] = v;
    }
}

// ---------------------------------------------------------------------------
// Gather: one warp per token. Lane l owns output columns bc = l and l+32.
// m23 row loads: 8x LDG.128 per lane (4KB slice, coalesced).
// g1 coef pairs come from smem via LDS.128 (core1 = 25.6KB staged per CTA).
// Reduction paired over (even r, odd r) -> fma.rn.f32x2, final lo+hi add.
// ---------------------------------------------------------------------------
__device__ __forceinline__ unsigned long long ffma2(unsigned long long a,
                                                    unsigned long long b,
                                                    unsigned long long c) {
    unsigned long long d;
    asm("fma.rn.f32x2 %0, %1, %2, %3;" : "=l"(d) : "l"(a), "l"(b), "l"(c));
    return d;
}

__global__ __launch_bounds__(256, 3)
void gather_kernel(const int* __restrict__ x,
                   const float* __restrict__ core1,
                   float* __restrict__ out,
                   int n_tokens) {
    __shared__ __align__(16) float s_g1[C1_ELEMS];   // [i1][a][r], 25.6KB
    {
        const float4* g = (const float4*)core1;
        float4* s = (float4*)s_g1;
        for (int i = threadIdx.x; i < C1_ELEMS / 4; i += 256) s[i] = g[i];
    }
    __syncthreads();

    const int is64  = g_is64;
    const int lane  = threadIdx.x & 31;
    const int warp  = (blockIdx.x * 256 + threadIdx.x) >> 5;
    const int nwarp = gridDim.x * 8;

    for (int j = warp; j < n_tokens; j += nwarp) {
        unsigned id = (unsigned)(is64 ? x[2 * j] : x[j]);
        unsigned i1 = id / 3600u;
        unsigned pr = id - i1 * 3600u;

        const ulonglong2* mrow = (const ulonglong2*)(g_m23 + pr * PAIR_ELEMS);
        // row bc = lane (A) and bc = lane+32 (B); each row = 16 floats = 4x b64x2
        ulonglong2 A0 = mrow[lane * 4 + 0];
        ulonglong2 A1 = mrow[lane * 4 + 1];
        ulonglong2 A2 = mrow[lane * 4 + 2];
        ulonglong2 A3 = mrow[lane * 4 + 3];
        ulonglong2 B0 = mrow[(lane + 32) * 4 + 0];
        ulonglong2 B1 = mrow[(lane + 32) * 4 + 1];
        ulonglong2 B2 = mrow[(lane + 32) * 4 + 2];
        ulonglong2 B3 = mrow[(lane + 32) * 4 + 3];

        const ulonglong2* g1p = (const ulonglong2*)(s_g1 + i1 * 128);
        float* op = out + (size_t)j * 512 + lane;

#pragma unroll
        for (int a = 0; a < 8; a++) {
            ulonglong2 c0 = g1p[a * 4 + 0];
            ulonglong2 c1 = g1p[a * 4 + 1];
            ulonglong2 c2 = g1p[a * 4 + 2];
            ulonglong2 c3 = g1p[a * 4 + 3];

            unsigned long long accA = ffma2(c0.x, A0.x, 0ull);
            accA = ffma2(c0.y, A0.y, accA);
            accA = ffma2(c1.x, A1.x, accA);
            accA = ffma2(c1.y, A1.y, accA);
            accA = ffma2(c2.x, A2.x, accA);
            accA = ffma2(c2.y, A2.y, accA);
            accA = ffma2(c3.x, A3.x, accA);
            accA = ffma2(c3.y, A3.y, accA);

            unsigned long long accB = ffma2(c0.x, B0.x, 0ull);
            accB = ffma2(c0.y, B0.y, accB);
            accB = ffma2(c1.x, B1.x, accB);
            accB = ffma2(c1.y, B1.y, accB);
            accB = ffma2(c2.x, B2.x, accB);
            accB = ffma2(c2.y, B2.y, accB);
            accB = ffma2(c3.x, B3.x, accB);
            accB = ffma2(c3.y, B3.y, accB);

            float2 fA = *(float2*)&accA;
            float2 fB = *(float2*)&accB;
            op[a * 64]      = fA.x + fA.y;
            op[a * 64 + 32] = fB.x + fB.y;
        }
    }
}

// ---------------------------------------------------------------------------
extern "C" void kernel_launch(void* const* d_in, const int* in_sizes, int n_in,
                              void* d_out, int out_size) {
    const void*  x  = nullptr;
    const float* c1 = nullptr;
    const float* c2 = nullptr;
    const float* c3 = nullptr;
    int n_tokens = 131072;

    for (int i = 0; i < n_in; i++) {
        switch (in_sizes[i]) {
            case C1_ELEMS: c1 = (const float*)d_in[i]; break;
            case C2_ELEMS: c2 = (const float*)d_in[i]; break;
            case C3_ELEMS: c3 = (const float*)d_in[i]; break;
            default:       x  = d_in[i]; n_tokens = in_sizes[i]; break;
        }
    }

    detect_kernel<<<1, 32>>>((const int*)x);
    build_table_kernel<<<N_PAIRS, 128>>>(c2, c3);
    gather_kernel<<<444, 256>>>((const int*)x, c1, (float*)d_out, n_tokens);
}

// round 3
// speedup vs baseline: 1.1762x; 1.1762x over previous
#include <cuda_runtime.h>

// TT embedding, binned by (i2,i3) pair.
// vocab = 50*60*60, emb = 8*8*8 = 512, rank 16, T = 131072 tokens.
//
// Pipeline (single stream, graph-capturable, all __device__ state rewritten
// every launch sequence):
//   k_init    : zero pair counters + detect int32-vs-int64 x layout
//   k_build   : m23[p][r/4][bc][r%4] = sum_s core2[i2][r][b][s]*core3[i3][s][c]
//   k_hist    : count tokens per pair (global atomics)
//   k_scan    : exclusive prefix sum over 3600 counters (1 CTA)
//   k_scatter : bin token (index | i1<<18) by pair
//   k_compute : persistent CTAs; per pair, m23 row staged to smem once, each
//               warp holds its two bc-rows in registers, then per token only
//               g1 smem broadcasts + ffma2 chains + coalesced float2 stores.

#define NP        3600
#define C1_ELEMS  6400      // 50*8*16
#define C2_ELEMS  122880    // 60*16*8*16
#define C3_ELEMS  7680      // 60*16*8
#define MAXT      (1 << 18)

__device__ __align__(16) float g_m23[NP * 1024];   // 14.75 MB (L2-resident)
__device__ int g_cnt[NP];
__device__ int g_ofs[NP];
__device__ int g_cur[NP];
__device__ int g_bin[MAXT];
__device__ int g_is64;

// ---------------------------------------------------------------------------
__global__ void k_init(const int* __restrict__ x) {
    int t = blockIdx.x * blockDim.x + threadIdx.x;
    if (t < NP) g_cnt[t] = 0;
    if (blockIdx.x == 0 && threadIdx.x < 32) {
        int z = 0;
#pragma unroll
        for (int k = 0; k < 4; k++) {
            int idx = 2 * (threadIdx.x + 32 * k) + 1;   // odd 32-bit words
            z += (x[idx] == 0);
        }
#pragma unroll
        for (int o = 16; o; o >>= 1) z += __shfl_xor_sync(0xFFFFFFFFu, z, o);
        if (threadIdx.x == 0) g_is64 = (z >= 120) ? 1 : 0;
    }
}

// ---------------------------------------------------------------------------
// One block per (i2,i3). Output layout: m23[p][rh][bc][rl], rh = r>>2, rl = r&3.
// ---------------------------------------------------------------------------
__global__ void k_build(const float* __restrict__ core2,
                        const float* __restrict__ core3) {
    __shared__ __align__(16) float c2s[2048];   // [r][b][s]
    __shared__ __align__(16) float c3s[128];    // [s][c]
    int p  = blockIdx.x;
    int i2 = p / 60;
    int i3 = p - i2 * 60;
    {
        const float4* g = (const float4*)(core2 + i2 * 2048);
        float4* s = (float4*)c2s;
        for (int i = threadIdx.x; i < 512; i += 128) s[i] = g[i];
        if (threadIdx.x < 32)
            ((float4*)c3s)[threadIdx.x] = ((const float4*)(core3 + i3 * 128))[threadIdx.x];
    }
    __syncthreads();

    int bc  = threadIdx.x & 63;
    int rh2 = threadIdx.x >> 6;        // 0/1 -> r in [rh2*8, rh2*8+8)
    int b   = bc >> 3;
    int c   = bc & 7;
    float v[8];
#pragma unroll
    for (int rr = 0; rr < 8; rr++) {
        int r = rh2 * 8 + rr;
        const float* c2row = c2s + r * 128 + b * 16;
        float acc = 0.0f;
#pragma unroll
        for (int s = 0; s < 16; s++) acc += c2row[s] * c3s[s * 8 + c];
        v[rr] = acc;
    }
    float* dst = g_m23 + p * 1024;
    *(float4*)(dst + (2 * rh2 + 0) * 256 + bc * 4) = make_float4(v[0], v[1], v[2], v[3]);
    *(float4*)(dst + (2 * rh2 + 1) * 256 + bc * 4) = make_float4(v[4], v[5], v[6], v[7]);
}

// ---------------------------------------------------------------------------
__global__ void k_hist(const int* __restrict__ x, int n) {
    int is64 = g_is64;
    int stride = gridDim.x * blockDim.x;
    for (int j = blockIdx.x * blockDim.x + threadIdx.x; j < n; j += stride) {
        unsigned id = (unsigned)(is64 ? x[2 * j] : x[j]);
        atomicAdd(&g_cnt[id % 3600u], 1);
    }
}

// ---------------------------------------------------------------------------
__global__ void k_scan() {     // 1 CTA, 1024 threads
    __shared__ int s_sum[1024];
    int t = threadIdx.x;
    int base = t * 4;
    int c[4];
    int local = 0;
#pragma unroll
    for (int i = 0; i < 4; i++) {
        int idx = base + i;
        c[i] = (idx < NP) ? g_cnt[idx] : 0;
        local += c[i];
    }
    s_sum[t] = local;
    __syncthreads();
    for (int d = 1; d < 1024; d <<= 1) {
        int v = s_sum[t];
        int u = (t >= d) ? s_sum[t - d] : 0;
        __syncthreads();
        s_sum[t] = v + u;
        __syncthreads();
    }
    int run = (t == 0) ? 0 : s_sum[t - 1];
#pragma unroll
    for (int i = 0; i < 4; i++) {
        int idx = base + i;
        if (idx < NP) { g_ofs[idx] = run; g_cur[idx] = run; run += c[i]; }
    }
}

// ---------------------------------------------------------------------------
__global__ void k_scatter(const int* __restrict__ x, int n) {
    int is64 = g_is64;
    int stride = gridDim.x * blockDim.x;
    for (int j = blockIdx.x * blockDim.x + threadIdx.x; j < n; j += stride) {
        unsigned id = (unsigned)(is64 ? x[2 * j] : x[j]);
        unsigned i1 = id / 3600u;
        unsigned p  = id - i1 * 3600u;
        int pos = atomicAdd(&g_cur[p], 1);
        g_bin[pos] = j | ((int)i1 << 18);
    }
}

// ---------------------------------------------------------------------------
__device__ __forceinline__ unsigned long long ffma2(unsigned long long a,
                                                    unsigned long long b,
                                                    unsigned long long c) {
    unsigned long long d;
    asm("fma.rn.f32x2 %0, %1, %2, %3;" : "=l"(d) : "l"(a), "l"(b), "l"(c));
    return d;
}

__global__ __launch_bounds__(256, 2)
void k_compute(const float* __restrict__ core1, float* __restrict__ out) {
    __shared__ __align__(16) float  s_g1[C1_ELEMS];   // 25.6 KB, [i1][a][r]
    __shared__ __align__(16) float4 s_m[256];         // 4 KB, [rh][bc] (rl packed)

    {
        const float4* g = (const float4*)core1;
        float4* s = (float4*)s_g1;
        for (int i = threadIdx.x; i < C1_ELEMS / 4; i += 256) s[i] = g[i];
    }

    const int lane = threadIdx.x & 31;
    const int w    = threadIdx.x >> 5;

    for (int p = blockIdx.x; p < NP; p += gridDim.x) {
        __syncthreads();                               // prev pair reg-loads done
        s_m[threadIdx.x] = ((const float4*)g_m23)[p * 256 + threadIdx.x];
        __syncthreads();

        // rows bc = 2*lane (P) and 2*lane+1 (Q): 16 floats each, pairs (r,r+1)
        unsigned long long Pp[8], Qp[8];
#pragma unroll
        for (int h = 0; h < 4; h++) {
            float4 fp = s_m[h * 64 + 2 * lane];
            float4 fq = s_m[h * 64 + 2 * lane + 1];
            Pp[2 * h]     = *(unsigned long long*)&fp.x;
            Pp[2 * h + 1] = *(unsigned long long*)&fp.z;
            Qp[2 * h]     = *(unsigned long long*)&fq.x;
            Qp[2 * h + 1] = *(unsigned long long*)&fq.z;
        }

        int start = g_ofs[p];
        int end   = start + g_cnt[p];

        for (int t = start + w; t < end; t += 8) {
            int e  = g_bin[t];
            int j  = e & 0x3FFFF;
            int i1 = e >> 18;
            const ulonglong2* g1p = (const ulonglong2*)(s_g1 + i1 * 128);
            float* op = out + (size_t)j * 512 + 2 * lane;

#pragma unroll
            for (int a = 0; a < 8; a++) {
                ulonglong2 C0 = g1p[a * 4 + 0];
                ulonglong2 C1 = g1p[a * 4 + 1];
                ulonglong2 C2 = g1p[a * 4 + 2];
                ulonglong2 C3 = g1p[a * 4 + 3];

                unsigned long long aP = ffma2(C0.x, Pp[0], 0ull);
                unsigned long long aQ = ffma2(C0.x, Qp[0], 0ull);
                aP = ffma2(C0.y, Pp[1], aP);  aQ = ffma2(C0.y, Qp[1], aQ);
                aP = ffma2(C1.x, Pp[2], aP);  aQ = ffma2(C1.x, Qp[2], aQ);
                aP = ffma2(C1.y, Pp[3], aP);  aQ = ffma2(C1.y, Qp[3], aQ);
                aP = ffma2(C2.x, Pp[4], aP);  aQ = ffma2(C2.x, Qp[4], aQ);
                aP = ffma2(C2.y, Pp[5], aP);  aQ = ffma2(C2.y, Qp[5], aQ);
                aP = ffma2(C3.x, Pp[6], aP);  aQ = ffma2(C3.x, Qp[6], aQ);
                aP = ffma2(C3.y, Pp[7], aP);  aQ = ffma2(C3.y, Qp[7], aQ);

                float2 fP = *(float2*)&aP;
                float2 fQ = *(float2*)&aQ;
                *(float2*)(op + a * 64) = make_float2(fP.x + fP.y, fQ.x + fQ.y);
            }
        }
    }
}

// ---------------------------------------------------------------------------
extern "C" void kernel_launch(void* const* d_in, const int* in_sizes, int n_in,
                              void* d_out, int out_size) {
    const void*  x  = nullptr;
    const float* c1 = nullptr;
    const float* c2 = nullptr;
    const float* c3 = nullptr;
    int n_tokens = 131072;

    for (int i = 0; i < n_in; i++) {
        switch (in_sizes[i]) {
            case C1_ELEMS: c1 = (const float*)d_in[i]; break;
            case C2_ELEMS: c2 = (const float*)d_in[i]; break;
            case C3_ELEMS: c3 = (const float*)d_in[i]; break;
            default:       x  = d_in[i]; n_tokens = in_sizes[i]; break;
        }
    }

    k_init   <<<4, 1024>>>((const int*)x);
    k_build  <<<NP, 128>>>(c2, c3);
    k_hist   <<<256, 256>>>((const int*)x, n_tokens);
    k_scan   <<<1, 1024>>>();
    k_scatter<<<256, 256>>>((const int*)x, n_tokens);
    k_compute<<<296, 256>>>(c1, (float*)d_out);
}

// round 6
// speedup vs baseline: 1.4905x; 1.2673x over previous
#include <cuda_runtime.h>

// TT embedding, binned by full unique id (key = p*50 + i1, p = (i2,i3) pair).
// vocab = 50*60*60 = 180000, emb = 512, rank 16, T = 131072 tokens.
//
// Launch chain (graph-capturable, no allocs):
//   k_build   : m23 pair table (3600 x 1KB rows) + zero hist counters + dtype detect
//   k_hist    : count tokens per key (180K keys)
//   k_scanA   : per-256-block exclusive scan of counts -> g_loc, block sums -> g_bsum
//   k_scanB   : exclusive scan of 704 block sums (1 CTA, shuffle scan)
//   k_scatter : g_bin[g_loc[key]+g_bsum[key>>8]+rank] = token index
//   k_compute : persistent CTAs over pairs; m23 row in smem/regs; per UNIQUE id
//               one 128-ffma2 contraction, per duplicate only 8 coalesced stores.

#define NP        3600
#define NKEY      180224          // 180000 padded to 704*256
#define NB        704
#define C1_ELEMS  6400            // 50*8*16
#define C2_ELEMS  122880          // 60*16*8*16
#define C3_ELEMS  7680            // 60*16*8
#define MAXT      (1 << 18)

__device__ __align__(16) float g_m23[NP * 1024];   // 14.75 MB, L2-resident
__device__ int g_cnt[NKEY];
__device__ int g_loc[NKEY];
__device__ int g_cur[NKEY];
__device__ int g_bsum[NB];
__device__ int g_bin[MAXT];
__device__ int g_is64;

// ---------------------------------------------------------------------------
// k_build: pair table + zero counters + dtype detect (fused).
// ---------------------------------------------------------------------------
__global__ void k_build(const float* __restrict__ core2,
                        const float* __restrict__ core3,
                        const int* __restrict__ x) {
    __shared__ __align__(16) float c2s[2048];   // [r][b][s]
    __shared__ __align__(16) float c3s[128];    // [s][c]
    int p  = blockIdx.x;
    int gt = p * 128 + threadIdx.x;
    if (gt < NKEY) { g_cnt[gt] = 0; g_cur[gt] = 0; }

    if (p == 0 && threadIdx.x < 32) {           // int64-vs-int32 detect
        int z = 0;
#pragma unroll
        for (int k = 0; k < 4; k++) z += (x[2 * (threadIdx.x + 32 * k) + 1] == 0);
#pragma unroll
        for (int o = 16; o; o >>= 1) z += __shfl_xor_sync(0xFFFFFFFFu, z, o);
        if (threadIdx.x == 0) g_is64 = (z >= 120) ? 1 : 0;
    }

    int i2 = p / 60;
    int i3 = p - i2 * 60;
    {
        const float4* g = (const float4*)(core2 + i2 * 2048);
        float4* s = (float4*)c2s;
        for (int i = threadIdx.x; i < 512; i += 128) s[i] = g[i];
        if (threadIdx.x < 32)
            ((float4*)c3s)[threadIdx.x] = ((const float4*)(core3 + i3 * 128))[threadIdx.x];
    }
    __syncthreads();

    int bc  = threadIdx.x & 63;
    int rh2 = threadIdx.x >> 6;                 // r in [rh2*8, rh2*8+8)
    int b   = bc >> 3;
    int c   = bc & 7;
    float v[8];
#pragma unroll
    for (int rr = 0; rr < 8; rr++) {
        const float* c2row = c2s + (rh2 * 8 + rr) * 128 + b * 16;
        float acc = 0.0f;
#pragma unroll
        for (int s = 0; s < 16; s++) acc += c2row[s] * c3s[s * 8 + c];
        v[rr] = acc;
    }
    // layout: m23[p][rh][bc][rl], rh = r>>2, rl = r&3
    float* dst = g_m23 + p * 1024;
    *(float4*)(dst + (2 * rh2 + 0) * 256 + bc * 4) = make_float4(v[0], v[1], v[2], v[3]);
    *(float4*)(dst + (2 * rh2 + 1) * 256 + bc * 4) = make_float4(v[4], v[5], v[6], v[7]);
}

// ---------------------------------------------------------------------------
__global__ void k_hist(const int* __restrict__ x, int n) {
    int is64 = g_is64;
    int stride = gridDim.x * blockDim.x;
    for (int j = blockIdx.x * blockDim.x + threadIdx.x; j < n; j += stride) {
        unsigned id = (unsigned)(is64 ? x[2 * j] : x[j]);
        unsigned i1 = id / 3600u;
        unsigned p  = id - i1 * 3600u;
        atomicAdd(&g_cnt[p * 50 + i1], 1);
    }
}

// ---------------------------------------------------------------------------
// shuffle-based exclusive block scan; returns exclusive prefix, s_w[nw-1]
// ends up holding the block total (inclusive of last warp).
// ---------------------------------------------------------------------------
__device__ __forceinline__ int block_exscan(int v, int* s_w) {
    int lane = threadIdx.x & 31, wid = threadIdx.x >> 5;
    int nw = blockDim.x >> 5;
    int xi = v;
#pragma unroll
    for (int o = 1; o < 32; o <<= 1) {
        int u = __shfl_up_sync(0xFFFFFFFFu, xi, o);
        if (lane >= o) xi += u;
    }
    if (lane == 31) s_w[wid] = xi;
    __syncthreads();
    if (wid == 0) {
        int y = (lane < nw) ? s_w[lane] : 0;
#pragma unroll
        for (int o = 1; o < 32; o <<= 1) {
            int u = __shfl_up_sync(0xFFFFFFFFu, y, o);
            if (lane >= o) y += u;
        }
        if (lane < nw) s_w[lane] = y;
    }
    __syncthreads();
    int base = wid ? s_w[wid - 1] : 0;
    return base + xi - v;
}

__global__ void k_scanA() {                     // 704 blocks x 256
    __shared__ int s_w[32];
    int i = blockIdx.x * 256 + threadIdx.x;
    int v = g_cnt[i];
    int ex = block_exscan(v, s_w);
    g_loc[i] = ex;
    if (threadIdx.x == 255) g_bsum[blockIdx.x] = ex + v;
}

__global__ void k_scanB() {                     // 1 block x 1024
    __shared__ int s_w[32];
    int t = threadIdx.x;
    int v = (t < NB) ? g_bsum[t] : 0;
    int ex = block_exscan(v, s_w);
    if (t < NB) g_bsum[t] = ex;
}

// ---------------------------------------------------------------------------
__global__ void k_scatter(const int* __restrict__ x, int n) {
    int is64 = g_is64;
    int stride = gridDim.x * blockDim.x;
    for (int j = blockIdx.x * blockDim.x + threadIdx.x; j < n; j += stride) {
        unsigned id = (unsigned)(is64 ? x[2 * j] : x[j]);
        unsigned i1 = id / 3600u;
        unsigned p  = id - i1 * 3600u;
        int key = p * 50 + i1;
        int ofs = g_loc[key] + g_bsum[key >> 8];
        g_bin[ofs + atomicAdd(&g_cur[key], 1)] = j;
    }
}

// ---------------------------------------------------------------------------
__device__ __forceinline__ unsigned long long ffma2(unsigned long long a,
                                                    unsigned long long b,
                                                    unsigned long long c) {
    unsigned long long d;
    asm("fma.rn.f32x2 %0, %1, %2, %3;" : "=l"(d) : "l"(a), "l"(b), "l"(c));
    return d;
}

__global__ __launch_bounds__(256, 2)
void k_compute(const float* __restrict__ core1, float* __restrict__ out) {
    __shared__ __align__(16) float  s_g1[C1_ELEMS];   // 25.6 KB  [i1][a][r]
    __shared__ __align__(16) float4 s_m[256];         // 4 KB     [rh][bc]

    {
        const float4* g = (const float4*)core1;
        float4* s = (float4*)s_g1;
        for (int i = threadIdx.x; i < C1_ELEMS / 4; i += 256) s[i] = g[i];
    }

    const int lane = threadIdx.x & 31;
    const int w    = threadIdx.x >> 5;

    for (int p = blockIdx.x; p < NP; p += gridDim.x) {
        __syncthreads();                               // prior pair's reg-loads done
        s_m[threadIdx.x] = ((const float4*)g_m23)[p * 256 + threadIdx.x];
        __syncthreads();

        // rows bc = 2*lane (P) and 2*lane+1 (Q), r paired (even,odd)
        unsigned long long Pp[8], Qp[8];
#pragma unroll
        for (int h = 0; h < 4; h++) {
            float4 fp = s_m[h * 64 + 2 * lane];
            float4 fq = s_m[h * 64 + 2 * lane + 1];
            Pp[2 * h]     = *(unsigned long long*)&fp.x;
            Pp[2 * h + 1] = *(unsigned long long*)&fp.z;
            Qp[2 * h]     = *(unsigned long long*)&fq.x;
            Qp[2 * h + 1] = *(unsigned long long*)&fq.z;
        }

        // warps split the 50 i1 values of this pair
        for (int i1 = w; i1 < 50; i1 += 8) {
            int key = p * 50 + i1;
            int cnt = g_cnt[key];
            if (cnt == 0) continue;
            int ofs = g_loc[key] + g_bsum[key >> 8];

            const ulonglong2* g1p = (const ulonglong2*)(s_g1 + i1 * 128);
            float2 o[8];
#pragma unroll
            for (int a = 0; a < 8; a++) {
                ulonglong2 C0 = g1p[a * 4 + 0];
                ulonglong2 C1 = g1p[a * 4 + 1];
                ulonglong2 C2 = g1p[a * 4 + 2];
                ulonglong2 C3 = g1p[a * 4 + 3];

                unsigned long long aP = ffma2(C0.x, Pp[0], 0ull);
                unsigned long long aQ = ffma2(C0.x, Qp[0], 0ull);
                aP = ffma2(C0.y, Pp[1], aP);  aQ = ffma2(C0.y, Qp[1], aQ);
                aP = ffma2(C1.x, Pp[2], aP);  aQ = ffma2(C1.x, Qp[2], aQ);
                aP = ffma2(C1.y, Pp[3], aP);  aQ = ffma2(C1.y, Qp[3], aQ);
                aP = ffma2(C2.x, Pp[4], aP);  aQ = ffma2(C2.x, Qp[4], aQ);
                aP = ffma2(C2.y, Pp[5], aP);  aQ = ffma2(C2.y, Qp[5], aQ);
                aP = ffma2(C3.x, Pp[6], aP);  aQ = ffma2(C3.x, Qp[6], aQ);
                aP = ffma2(C3.y, Pp[7], aP);  aQ = ffma2(C3.y, Qp[7], aQ);

                float2 fP = *(float2*)&aP;
                float2 fQ = *(float2*)&aQ;
                o[a] = make_float2(fP.x + fP.y, fQ.x + fQ.y);
            }

            // replay stores for every duplicate token of this id
            for (int t = 0; t < cnt; t++) {
                int j = g_bin[ofs + t];
                float* op = out + (size_t)j * 512 + 2 * lane;
#pragma unroll
                for (int a = 0; a < 8; a++)
                    __stcs((float2*)(op + a * 64), o[a]);
            }
        }
    }
}

// ---------------------------------------------------------------------------
extern "C" void kernel_launch(void* const* d_in, const int* in_sizes, int n_in,
                              void* d_out, int out_size) {
    const void*  x  = nullptr;
    const float* c1 = nullptr;
    const float* c2 = nullptr;
    const float* c3 = nullptr;
    int n_tokens = 131072;

    for (int i = 0; i < n_in; i++) {
        switch (in_sizes[i]) {
            case C1_ELEMS: c1 = (const float*)d_in[i]; break;
            case C2_ELEMS: c2 = (const float*)d_in[i]; break;
            case C3_ELEMS: c3 = (const float*)d_in[i]; break;
            default:       x  = d_in[i]; n_tokens = in_sizes[i]; break;
        }
    }

    k_build  <<<NP, 128>>>(c2, c3, (const int*)x);
    k_hist   <<<256, 256>>>((const int*)x, n_tokens);
    k_scanA  <<<NB, 256>>>();
    k_scanB  <<<1, 1024>>>();
    k_scatter<<<256, 256>>>((const int*)x, n_tokens);
    k_compute<<<296, 256>>>(c1, (float*)d_out);
}